// round 11
// baseline (speedup 1.0000x reference)
#include <cuda_runtime.h>
#include <math.h>

#define BB   2
#define HH   16
#define TT   2048
#define DH   64
#define DD   1024
#define NC   10      // candidates carried into fp64 re-rank (k=8 + 2 margin)
#define JT   128     // key-columns per attention tile

// -------- scratch (device globals; no allocation allowed) --------
__device__ float g_q[BB*HH*TT*DH];
__device__ float g_k[BB*HH*TT*DH];
__device__ float g_v[BB*HH*TT*DH];
__device__ float g_att[BB*TT*DD];

// ============================================================================
// SGEMM (NT): C[m][n] = sum_k A[m][k] * B[n][k]
// BM=BN=128, BK=16, 256 threads, 8x8 per thread.
// Double-buffered smem -> ONE __syncthreads per k-tile. Register prefetch of
// the next k-tile. Two-level accumulation (flush every 32 k-steps) keeps the
// fp32 rounding chain short (q/k must track the reference to ~1e-7 so the
// top-k selection does not flip).
// A == nullptr  -> read A from the device-global g_att (out-proj input).
// scatter == 1  -> QKV projection: scatter into g_q/g_k/g_v, head-split layout.
// Requires K % 32 == 0 (K = 1024 for both uses).
// ============================================================================
__global__ __launch_bounds__(256)
void sgemm_nt(const float* __restrict__ A, const float* __restrict__ B,
              float* __restrict__ C, int M, int N, int K, int scatter)
{
    __shared__ float As[2][16][132];
    __shared__ float Bs[2][16][132];

    const float* Abase = A ? A : (const float*)g_att;

    const int tid = threadIdx.x;
    const int m0  = blockIdx.y * 128;
    const int n0  = blockIdx.x * 128;
    const int tx  = tid & 15;
    const int ty  = tid >> 4;
    const int lr  = tid >> 2;          // 0..63
    const int lc  = (tid & 3) << 2;    // 0,4,8,12

    float acc[8][8];
    float cacc[8][8];
    #pragma unroll
    for (int i = 0; i < 8; i++)
        #pragma unroll
        for (int j = 0; j < 8; j++) { acc[i][j] = 0.f; cacc[i][j] = 0.f; }

    const float* Ap = Abase + (size_t)(m0 + lr) * K + lc;
    const float* Bp = B     + (size_t)(n0 + lr) * K + lc;

    // prologue: load first k-tile into registers
    float4 a0 = *(const float4*)(Ap);
    float4 a1 = *(const float4*)(Ap + (size_t)64 * K);
    float4 b0 = *(const float4*)(Bp);
    float4 b1 = *(const float4*)(Bp + (size_t)64 * K);

    for (int k0 = 0; k0 < K; k0 += 16) {
        const int p = (k0 >> 4) & 1;
        As[p][lc+0][lr]    = a0.x; As[p][lc+1][lr]    = a0.y; As[p][lc+2][lr]    = a0.z; As[p][lc+3][lr]    = a0.w;
        As[p][lc+0][lr+64] = a1.x; As[p][lc+1][lr+64] = a1.y; As[p][lc+2][lr+64] = a1.z; As[p][lc+3][lr+64] = a1.w;
        Bs[p][lc+0][lr]    = b0.x; Bs[p][lc+1][lr]    = b0.y; Bs[p][lc+2][lr]    = b0.z; Bs[p][lc+3][lr]    = b0.w;
        Bs[p][lc+0][lr+64] = b1.x; Bs[p][lc+1][lr+64] = b1.y; Bs[p][lc+2][lr+64] = b1.z; Bs[p][lc+3][lr+64] = b1.w;
        __syncthreads();

        // prefetch next tile (hidden under compute)
        int kn = k0 + 16;
        if (kn < K) {
            a0 = *(const float4*)(Ap + kn);
            a1 = *(const float4*)(Ap + (size_t)64 * K + kn);
            b0 = *(const float4*)(Bp + kn);
            b1 = *(const float4*)(Bp + (size_t)64 * K + kn);
        }

        #pragma unroll
        for (int kk = 0; kk < 16; kk++) {
            float a[8], b[8];
            *(float4*)&a[0] = *(const float4*)&As[p][kk][ty*8];
            *(float4*)&a[4] = *(const float4*)&As[p][kk][ty*8 + 4];
            *(float4*)&b[0] = *(const float4*)&Bs[p][kk][tx*8];
            *(float4*)&b[4] = *(const float4*)&Bs[p][kk][tx*8 + 4];
            #pragma unroll
            for (int i = 0; i < 8; i++)
                #pragma unroll
                for (int j = 0; j < 8; j++)
                    cacc[i][j] = fmaf(a[i], b[j], cacc[i][j]);
        }

        if (k0 & 16) {   // flush every 32 k-steps (K % 32 == 0)
            #pragma unroll
            for (int i = 0; i < 8; i++)
                #pragma unroll
                for (int j = 0; j < 8; j++) { acc[i][j] += cacc[i][j]; cacc[i][j] = 0.f; }
        }
        // no second barrier: next iteration writes the OTHER smem buffer; the
        // barrier at its top guarantees compute(k0) finished before reuse.
    }

    if (!scatter) {
        #pragma unroll
        for (int i = 0; i < 8; i++) {
            float* cp = C + (size_t)(m0 + ty*8 + i) * N + n0 + tx*8;
            *(float4*)cp       = make_float4(acc[i][0], acc[i][1], acc[i][2], acc[i][3]);
            *(float4*)(cp + 4) = make_float4(acc[i][4], acc[i][5], acc[i][6], acc[i][7]);
        }
    } else {
        #pragma unroll
        for (int i = 0; i < 8; i++) {
            int t  = m0 + ty*8 + i;
            int b_ = t >> 11;          // /2048
            int tl = t & 2047;
            #pragma unroll
            for (int j = 0; j < 8; j++) {
                int o    = n0 + tx*8 + j;
                int part = o >> 10;        // 0=q 1=k 2=v
                int rem  = o & 1023;
                int h    = rem >> 6;
                int dhi  = rem & 63;
                float* dst = (part == 0) ? g_q : (part == 1) ? g_k : g_v;
                dst[(((size_t)(b_*HH + h)) * TT + tl) * DH + dhi] = acc[i][j];
            }
        }
    }
}

// ============================================================================
// Fused causal scores + streaming top-k + fp64 re-rank + softmax + sparse AV.
// Grid: (32 = B*H, 64 = T/32). CTA: 256 threads = 8 warps x 4 rows = 32 rows.
// K tiles of 128 columns; each thread computes a 4-row x 4-col score block
// (FFMA:LDS = 8:1 vs 3.2:1 before -> smem crossbar no longer the hard bound,
// and 4x fewer tiles means 4x fewer barriers).
// Lane-local top-8 per row over the lane's 4-column subset; warp merge to
// top-NC candidates; fp64 exact recompute decides the final top-8; softmax
// over kept; gather of <=8 V rows. Q pre-scaled by 1/8 at load (exact).
// ============================================================================
__device__ __forceinline__ void topk_insert(float v[8], int ix[8], float s, int j)
{
    float cv = s; int ci = j;
    #pragma unroll
    for (int p = 0; p < 8; p++) {
        if (cv > v[p]) {
            float tvv = v[p]; int tii = ix[p];
            v[p] = cv; ix[p] = ci;
            cv = tvv; ci = tii;
        }
    }
}

__global__ __launch_bounds__(256)
void attn_topk_kernel()
{
    __shared__ float ks[JT * 68];    // 128 key rows x 64 (+4 pad)
    __shared__ float qs[32 * 68];    // 32 query rows x 64 (+4 pad), pre-scaled

    const int bh   = blockIdx.x;
    const int qt   = (int)gridDim.y - 1 - (int)blockIdx.y;  // heavy tiles first
    const int row0 = qt * 32;
    const int tid  = threadIdx.x;
    const int wid  = tid >> 5;
    const int lane = tid & 31;

    const float* Qb = g_q + (size_t)bh * TT * DH;
    const float* Kb = g_k + (size_t)bh * TT * DH;
    const float* Vb = g_v + (size_t)bh * TT * DH;

    // load Q tile (32 rows x 64), scaled by 1/8 (power of two: exact)
    for (int idx = tid; idx < 32 * 16; idx += 256) {
        int r = idx >> 4, c = (idx & 15) << 2;
        float4 v = *(const float4*)(Qb + (size_t)(row0 + r) * DH + c);
        v.x *= 0.125f; v.y *= 0.125f; v.z *= 0.125f; v.w *= 0.125f;
        *(float4*)&qs[r * 68 + c] = v;
    }

    const int rbase = wid * 4;
    const int g0    = row0 + rbase;

    float tv[4][8];
    int   ti[4][8];
    #pragma unroll
    for (int r = 0; r < 4; r++)
        #pragma unroll
        for (int p = 0; p < 8; p++) { tv[r][p] = -INFINITY; ti[r][p] = 0; }

    const float4* qpr[4] = {
        (const float4*)(qs + (rbase + 0) * 68),
        (const float4*)(qs + (rbase + 1) * 68),
        (const float4*)(qs + (rbase + 2) * 68),
        (const float4*)(qs + (rbase + 3) * 68) };
    const float4* kp0 = (const float4*)(ks + (lane      ) * 68);
    const float4* kp1 = (const float4*)(ks + (lane + 32 ) * 68);
    const float4* kp2 = (const float4*)(ks + (lane + 64 ) * 68);
    const float4* kp3 = (const float4*)(ks + (lane + 96 ) * 68);

    const int ntiles = (row0 + 32 + JT - 1) / JT;

    // K-tile staging: each thread carries 8 float4 (tile = 128 rows x 64 = 2048 float4)
    float4 pk[8];
    #pragma unroll
    for (int i = 0; i < 8; i++) {
        int ii = tid + 256 * i;
        int r = ii >> 4, c = (ii & 15) << 2;
        pk[i] = *(const float4*)(Kb + (size_t)r * DH + c);
    }

    for (int tj = 0; tj < ntiles; tj++) {
        const int j0 = tj * JT;
        __syncthreads();
        #pragma unroll
        for (int i = 0; i < 8; i++) {
            int ii = tid + 256 * i;
            int r = ii >> 4, c = (ii & 15) << 2;
            *(float4*)&ks[r * 68 + c] = pk[i];
        }
        __syncthreads();
        if (tj + 1 < ntiles) {
            int jn = (tj + 1) * JT;
            #pragma unroll
            for (int i = 0; i < 8; i++) {
                int ii = tid + 256 * i;
                int r = ii >> 4, c = (ii & 15) << 2;
                pk[i] = *(const float4*)(Kb + (size_t)(jn + r) * DH + c);
            }
        }

        float s[4][4];
        #pragma unroll
        for (int r = 0; r < 4; r++)
            #pragma unroll
            for (int c = 0; c < 4; c++) s[r][c] = 0.f;

        #pragma unroll
        for (int d = 0; d < 16; d++) {
            float4 k0 = kp0[d];
            float4 k1 = kp1[d];
            float4 k2 = kp2[d];
            float4 k3 = kp3[d];
            #pragma unroll
            for (int r = 0; r < 4; r++) {
                float4 q = qpr[r][d];
                s[r][0] = fmaf(q.w, k0.w, fmaf(q.z, k0.z, fmaf(q.y, k0.y, fmaf(q.x, k0.x, s[r][0]))));
                s[r][1] = fmaf(q.w, k1.w, fmaf(q.z, k1.z, fmaf(q.y, k1.y, fmaf(q.x, k1.x, s[r][1]))));
                s[r][2] = fmaf(q.w, k2.w, fmaf(q.z, k2.z, fmaf(q.y, k2.y, fmaf(q.x, k2.x, s[r][2]))));
                s[r][3] = fmaf(q.w, k3.w, fmaf(q.z, k3.z, fmaf(q.y, k3.y, fmaf(q.x, k3.x, s[r][3]))));
            }
        }

        // topk update: 4 rows x 4 columns per thread
        #pragma unroll
        for (int r = 0; r < 4; r++) {
            const int gi = g0 + r;
            #pragma unroll
            for (int c = 0; c < 4; c++) {
                int j = j0 + c * 32 + lane;
                float sc = s[r][c];
                if (j <= gi && sc > tv[r][7]) topk_insert(tv[r], ti[r], sc, j);
            }
        }
    }

    const int b_ = bh >> 4;
    const int h  = bh & 15;

    #pragma unroll
    for (int r = 0; r < 4; r++) {
        int gi = g0 + r;

        // ---- merge lane-local top-8 -> global top-NC candidate indices ----
        int mi[NC];
        #pragma unroll
        for (int n = 0; n < NC; n++) {
            float head = tv[r][0];
            float best = head;
            #pragma unroll
            for (int off = 16; off > 0; off >>= 1)
                best = fmaxf(best, __shfl_xor_sync(0xffffffffu, best, off));
            unsigned bal = __ballot_sync(0xffffffffu, head == best);
            int owner = __ffs((int)bal) - 1;
            int idx = __shfl_sync(0xffffffffu, ti[r][0], owner);
            mi[n] = (best == -INFINITY) ? -1 : idx;
            if (lane == owner) {
                #pragma unroll
                for (int p = 0; p < 7; p++) { tv[r][p] = tv[r][p + 1]; ti[r][p] = ti[r][p + 1]; }
                tv[r][7] = -INFINITY;
            }
        }

        // ---- fp64 exact recompute of candidate scores (warp-cooperative) ----
        // qs already holds q/8 (exact scaling), so no extra scale here.
        const float* qrow = qs + (rbase + r) * 68;
        float q1 = qrow[lane];
        float q2 = qrow[lane + 32];
        double dv[NC];
        #pragma unroll
        for (int n = 0; n < NC; n++) {
            int j = mi[n];
            double p = 0.0;
            if (j >= 0) {
                const float* kr = Kb + (size_t)j * DH;
                p = (double)q1 * (double)kr[lane] + (double)q2 * (double)kr[lane + 32];
            }
            #pragma unroll
            for (int off = 16; off > 0; off >>= 1)
                p += __shfl_xor_sync(0xffffffffu, p, off);
            dv[n] = (j >= 0) ? p : -1.0e300;
        }

        // ---- select top keff by fp64 rank; softmax; sparse AV ----
        int keff = min(gi + 1, 8);
        double mx = dv[0];
        #pragma unroll
        for (int n = 1; n < NC; n++) if (dv[n] > mx) mx = dv[n];

        float w[NC];
        float den = 0.f;
        #pragma unroll
        for (int n = 0; n < NC; n++) {
            int rank = 0;
            #pragma unroll
            for (int m = 0; m < NC; m++) rank += (dv[m] > dv[n]) ? 1 : 0;
            bool keep = (mi[n] >= 0) && (rank < keff);
            float wn = keep ? __expf((float)(dv[n] - mx)) : 0.f;
            w[n] = wn;
            den += wn;
        }

        float o0 = 0.f, o1 = 0.f;
        #pragma unroll
        for (int n = 0; n < NC; n++) {
            if (w[n] > 0.f) {   // uniform across warp (mi, dv identical on all lanes)
                const float* vr = Vb + (size_t)mi[n] * DH;
                o0 = fmaf(w[n], vr[lane],      o0);
                o1 = fmaf(w[n], vr[lane + 32], o1);
            }
        }
        float inv = 1.f / den;
        float* op = g_att + ((size_t)b_ * TT + gi) * DD + h * DH;
        op[lane]      = o0 * inv;
        op[lane + 32] = o1 * inv;
    }
}

// ============================================================================
// launch — three kernel launches only; no CUDA API calls in the capture path.
// ============================================================================
extern "C" void kernel_launch(void* const* d_in, const int* in_sizes, int n_in,
                              void* d_out, int out_size)
{
    const float* x     = (const float*)d_in[0];   // (2,2048,1024)
    const float* w_qkv = (const float*)d_in[1];   // (3072,1024)
    const float* w_out = (const float*)d_in[2];   // (1024,1024)
    float* out = (float*)d_out;                   // (2,2048,1024)

    dim3 blk(256);
    // QKV projection + head-split scatter: M=4096, N=3072, K=1024
    sgemm_nt<<<dim3(3072 / 128, 4096 / 128), blk>>>(x, w_qkv, nullptr, 4096, 3072, 1024, 1);
    // fused causal scores + top-k + fp64 re-rank + softmax + sparse AV
    attn_topk_kernel<<<dim3(BB * HH, TT / 32), blk>>>();
    // output projection: M=4096, N=1024, K=1024  (A = g_att via nullptr)
    sgemm_nt<<<dim3(1024 / 128, 4096 / 128), blk>>>(nullptr, w_out, out, 4096, 1024, 1024, 0);
}